// round 16
// baseline (speedup 1.0000x reference)
#include <cuda_runtime.h>
#include <cuda_bf16.h>
#include <cstdint>

// Problem constants (Wisard_68401649156855)
#define ENTRY_SIZE 1024
#define N_CLASSES  10
#define TUPLE_SIZE 16
#define N_RAMS     64
#define N_ADDR     65536
#define BATCH      8192
#define WORDS_PER_ROW 32
#define N_GROUPS   (BATCH / 32)     // 256 groups of 32 samples

#define GPB 4                       // groups per block (128 samples)

// Scratch: bitsT[w][b]: bit k = samples[b][w*32+k]
__device__ unsigned g_bitsT[WORDS_PER_ROW * BATCH];
// Scratch: bitsE[grp][e]: bit k = samples[grp*32+k][e]  (entry-major)
__device__ unsigned g_bitsE[N_GROUPS * ENTRY_SIZE];

// ---------------------------------------------------------------------------
// Kernel 1: pack samples (int32 0/1) -> bit matrix. (unchanged, known correct)
// ---------------------------------------------------------------------------
__global__ void __launch_bounds__(256) wisard_pack_kernel(const int* __restrict__ samples)
{
    int gtid   = blockIdx.x * blockDim.x + threadIdx.x;
    int b      = gtid >> 5;            // warp = sample row
    int lane   = gtid & 31;

    const int4* base = (const int4*)(samples + (size_t)b * ENTRY_SIZE) + lane;
    int4 v[8];
    #pragma unroll
    for (int it = 0; it < 8; ++it)
        v[it] = base[it * 32];

    unsigned j   = lane >> 3;
    unsigned sh  = 4u * (lane & 7);

    #pragma unroll
    for (int it = 0; it < 8; ++it) {
        unsigned nib = (unsigned)(v[it].x != 0)
                     | ((unsigned)(v[it].y != 0) << 1)
                     | ((unsigned)(v[it].z != 0) << 2)
                     | ((unsigned)(v[it].w != 0) << 3);
        unsigned x = nib << sh;
        x |= __shfl_xor_sync(0xffffffffu, x, 1);
        x |= __shfl_xor_sync(0xffffffffu, x, 2);
        x |= __shfl_xor_sync(0xffffffffu, x, 4);
        if ((lane & 7) == 0)
            g_bitsT[(it * 4 + j) * BATCH + b] = x;
    }
}

// ---------------------------------------------------------------------------
// 32x32 bit-matrix transpose across a warp (block-swap butterfly).
// out lane j, bit k  =  in lane k, bit j.
// ---------------------------------------------------------------------------
__device__ __forceinline__ unsigned warp_bit_transpose(unsigned x, int lane)
{
    const unsigned masks[5] = { 0x0000FFFFu, 0x00FF00FFu, 0x0F0F0F0Fu,
                                0x33333333u, 0x55555555u };
    const int shifts[5] = { 16, 8, 4, 2, 1 };
    #pragma unroll
    for (int i = 0; i < 5; ++i) {
        int s = shifts[i];
        unsigned lm = masks[i];
        unsigned y = __shfl_xor_sync(0xffffffffu, x, s);
        if ((lane & s) == 0)
            x = (x & lm) | ((y & lm) << s);
        else
            x = (x & ~lm) | ((y & ~lm) >> s);
    }
    return x;
}

// ---------------------------------------------------------------------------
// Kernel 2: one-time transpose bitsT -> bitsE (entry-major sample words).
// warpId = grp*32 + w. Reads coalesced over lanes; writes coalesced.
// bitsE[grp*1024 + w*32 + j]: bit k = sample (grp*32+k)'s entry (w*32+j).
// ---------------------------------------------------------------------------
__global__ void __launch_bounds__(256) wisard_transposeE_kernel()
{
    int warpId = (blockIdx.x * 256 + threadIdx.x) >> 5;
    int lane   = threadIdx.x & 31;
    int grp    = warpId >> 5;          // 0..255
    int w      = warpId & 31;          // 0..31

    unsigned x = g_bitsT[w * BATCH + grp * 32 + lane];
    x = warp_bit_transpose(x, lane);
    g_bitsE[grp * ENTRY_SIZE + w * 32 + lane] = x;
}

// ---------------------------------------------------------------------------
// Kernel 3: main WiSARD lookup. GPB=4 groups (128 samples) per block.
// Grid: (BATCH/128, N_CLASSES) = 640 blocks. Block: 256 threads = 8 warps.
// Prologue: coalesced int4 copy of 4 groups' bitsE into smem (16 KB).
// Phase 2a: warp wid owns RAMs [wid*8, wid*8+8). Per RAM pair: one coalesced
//   128B LDG of the 32 tm indices, LDS gather of entry-words, butterfly ->
//   lane j holds (addr_{r+1}<<16)|addr_r for sample j of group g.
// Phase 2b: 32 independent gathers back-to-back per warp (MLP=32).
// Phase 3: cross-warp reduction per group.
// ---------------------------------------------------------------------------
__global__ void __launch_bounds__(256, 4) wisard_main_kernel(
    const int*   __restrict__ tuple_mapping,  // [N_CLASSES][ENTRY_SIZE]
    const float* __restrict__ ram_table,      // [N_CLASSES][N_RAMS][N_ADDR]
    float*       __restrict__ out)            // [BATCH][N_CLASSES]
{
    const int c    = blockIdx.y;
    const int bw   = blockIdx.x;               // 128-sample super-group
    const int tid  = threadIdx.x;
    const int wid  = tid >> 5;
    const int lane = tid & 31;

    __shared__ __align__(16) unsigned bitS_s[GPB * ENTRY_SIZE];  // 16 KB
    __shared__ float                  red[8][GPB][32];           // 4 KB

    // Prologue: coalesced copy of this block's 4 groups (4096 words).
    {
        const int4* src = (const int4*)(g_bitsE + bw * (GPB * ENTRY_SIZE));
        int4*       dst = (int4*)bitS_s;
        #pragma unroll
        for (int i = 0; i < (GPB * ENTRY_SIZE / 4) / 256; ++i)
            dst[i * 256 + tid] = src[i * 256 + tid];
    }
    __syncthreads();

    const float* tbl = ram_table + (size_t)c * (N_RAMS * N_ADDR);
    const int*   tm  = tuple_mapping + c * ENTRY_SIZE;

    // lane l -> tuple slot (r + (l>>4))*16 + 15 - (l&15)
    const int tm_off = (lane >> 4) * 16 + 15 - (lane & 15);

    // Hoisted: the 4 per-pair tm indices (coalesced 128B LDGs, independent).
    int idx0 = tm[(wid * 8 + 0) * 16 + tm_off];
    int idx1 = tm[(wid * 8 + 2) * 16 + tm_off];
    int idx2 = tm[(wid * 8 + 4) * 16 + tm_off];
    int idx3 = tm[(wid * 8 + 6) * 16 + tm_off];

    // Phase 2a: 16 butterflies -> 32 addresses (2 per word) across 4 groups.
    unsigned aw[4][GPB];
    #pragma unroll
    for (int g = 0; g < GPB; ++g) {
        aw[0][g] = warp_bit_transpose(bitS_s[g * ENTRY_SIZE + idx0], lane);
        aw[1][g] = warp_bit_transpose(bitS_s[g * ENTRY_SIZE + idx1], lane);
        aw[2][g] = warp_bit_transpose(bitS_s[g * ENTRY_SIZE + idx2], lane);
        aw[3][g] = warp_bit_transpose(bitS_s[g * ENTRY_SIZE + idx3], lane);
    }

    // Phase 2b: 32 independent gathers (lane = sample within group).
    float acc[GPB] = {0.f, 0.f, 0.f, 0.f};
    #pragma unroll
    for (int pair = 0; pair < 4; ++pair) {
        const int r = wid * 8 + pair * 2;
        const float* base = tbl + ((size_t)r << TUPLE_SIZE);
        #pragma unroll
        for (int g = 0; g < GPB; ++g) {
            float v0 = __ldg(base + (aw[pair][g] & 0xFFFFu));
            float v1 = __ldg(base + N_ADDR + (aw[pair][g] >> 16));
            acc[g] += v0 + v1;
        }
    }

    // Phase 3: reduce the 8 warp partials per (group, sample).
    #pragma unroll
    for (int g = 0; g < GPB; ++g)
        red[wid][g][lane] = acc[g];
    __syncthreads();

    if (wid < GPB) {
        float s = red[0][wid][lane];
        #pragma unroll
        for (int w = 1; w < 8; ++w) s += red[w][wid][lane];
        out[(bw * (GPB * 32) + wid * 32 + lane) * N_CLASSES + c] = s;
    }
}

// ---------------------------------------------------------------------------
// Launch
// ---------------------------------------------------------------------------
extern "C" void kernel_launch(void* const* d_in, const int* in_sizes, int n_in,
                              void* d_out, int out_size)
{
    const int*   samples       = (const int*)  d_in[0];  // [8192][1024] int32
    const int*   tuple_mapping = (const int*)  d_in[1];  // [10][1024]   int32
    const float* ram_table     = (const float*)d_in[2];  // [10][64][65536] float32
    float*       out           = (float*)d_out;          // [8192][10]   float32

    wisard_pack_kernel<<<(BATCH * 32) / 256, 256>>>(samples);
    wisard_transposeE_kernel<<<(N_GROUPS * 32 * 32) / 256, 256>>>();

    dim3 grid(BATCH / (GPB * 32), N_CLASSES);   // 64 x 10 = 640 blocks
    wisard_main_kernel<<<grid, 256>>>(tuple_mapping, ram_table, out);
}